// round 7
// baseline (speedup 1.0000x reference)
#include <cuda_runtime.h>
#include <math.h>
#include <stdint.h>

#define D_MODEL 1024
#define N_HEADS 16
#define DEPTH   64
#define BATCH   2
#define SEQ     2048
#define M_TOT   (BATCH * SEQ)   // 4096

// ---------------------------------------------------------------------------
// Scratch (no cudaMalloc allowed): device globals
// ---------------------------------------------------------------------------
__device__ float g_q[BATCH * N_HEADS * SEQ * DEPTH];   // [B,H,S,64]
__device__ float g_k[BATCH * N_HEADS * SEQ * DEPTH];
__device__ float g_v[BATCH * N_HEADS * SEQ * DEPTH];
__device__ float g_ao[M_TOT * D_MODEL];                // attention out [B,S,D]

// ---------------------------------------------------------------------------
// PTX helpers (baseline features only: mma.sync, ldmatrix — legal on sm_103)
// ---------------------------------------------------------------------------
__device__ __forceinline__ void mma_tf32(float c[4], const uint32_t a[4],
                                         const uint32_t b[2]) {
    asm volatile(
        "mma.sync.aligned.m16n8k8.row.col.f32.tf32.tf32.f32 "
        "{%0,%1,%2,%3}, {%4,%5,%6,%7}, {%8,%9}, {%0,%1,%2,%3};\n"
        : "+f"(c[0]), "+f"(c[1]), "+f"(c[2]), "+f"(c[3])
        : "r"(a[0]), "r"(a[1]), "r"(a[2]), "r"(a[3]),
          "r"(b[0]), "r"(b[1]));
}

// ldmatrix x4 on 32-bit data: each of the 4 result regs is the (lane/4, lane%4)
// b32 element of an 8x4 b32 (= 8x8 b16) matrix; lanes 0-7/8-15/16-23/24-31
// provide the 16B row addresses of matrices 0/1/2/3.
__device__ __forceinline__ void ldsm4(uint32_t r[4], uint32_t addr) {
    asm volatile("ldmatrix.sync.aligned.m8n8.x4.shared.b16 {%0,%1,%2,%3}, [%4];"
        : "=r"(r[0]), "=r"(r[1]), "=r"(r[2]), "=r"(r[3]) : "r"(addr));
}

__device__ __forceinline__ uint32_t smem_u32(const void* p) {
    uint32_t a;
    asm("{ .reg .u64 t; cvta.to.shared.u64 t, %1; cvt.u32.u64 %0, t; }"
        : "=r"(a) : "l"(p));
    return a;
}

__device__ __forceinline__ float tf32_round(float x) {
    uint32_t t;
    asm("cvt.rna.tf32.f32 %0, %1;" : "=r"(t) : "f"(x));
    return __uint_as_float(t);
}

// ---------------------------------------------------------------------------
// GEMM (tensor-core tf32): Y = X @ W^T + bias
// Block 128x128, BK=16, double-buffered smem, 8 warps (2m x 4n), warp 64x32.
// Fragments fed via ldmatrix.x4 (LDA=20 floats -> 5x16B row stride, odd ->
// conflict-free ldmatrix fetches).
// ---------------------------------------------------------------------------
#define BK   16
#define LDA  20
#define STAGEF (128 * LDA)

template <int HEAD_SPLIT>
__global__ __launch_bounds__(256, 2)
void gemm_mma_kernel(const float* __restrict__ X,
                     const float* __restrict__ W,
                     const float* __restrict__ bias,
                     float* __restrict__ Y)
{
    __shared__ float sA[2][STAGEF];
    __shared__ float sB[2][STAGEF];

    const int tid  = threadIdx.x;
    const int lane = tid & 31;
    const int wid  = tid >> 5;
    const int wm   = wid & 1;
    const int wn   = wid >> 1;
    const int g    = lane >> 2;
    const int t    = lane & 3;
    const int m0   = blockIdx.y * 128;
    const int n0   = blockIdx.x * 128;

    const int lrow = tid >> 2;
    const int lkq  = tid & 3;

    // ldmatrix per-lane source coordinates
    const int arow = wm * 64 + (lane & 15);
    const int acol = (lane & 16) ? 4 : 0;
    const int brow = wn * 32 + ((lane & 16) ? 8 : 0) + (lane & 7);
    const int bcol = (lane & 8) ? 4 : 0;
    const uint32_t sA_u = smem_u32(sA);
    const uint32_t sB_u = smem_u32(sB);

    float cacc[4][4][4];
    #pragma unroll
    for (int mf = 0; mf < 4; mf++)
        #pragma unroll
        for (int nf = 0; nf < 4; nf++)
            #pragma unroll
            for (int r = 0; r < 4; r++) cacc[mf][nf][r] = 0.0f;

    const float* Xb = X + (size_t)m0 * D_MODEL;
    const float* Wb = W + (size_t)n0 * D_MODEL;

    float4 ra[2], rb[2];

    #pragma unroll
    for (int j = 0; j < 2; j++) {
        ra[j] = *(const float4*)(Xb + (size_t)(lrow + j * 64) * D_MODEL + lkq * 4);
        rb[j] = *(const float4*)(Wb + (size_t)(lrow + j * 64) * D_MODEL + lkq * 4);
    }
    #pragma unroll
    for (int j = 0; j < 2; j++) {
        const int row = lrow + j * 64;
        float4 a = ra[j], b = rb[j];
        a.x = tf32_round(a.x); a.y = tf32_round(a.y);
        a.z = tf32_round(a.z); a.w = tf32_round(a.w);
        b.x = tf32_round(b.x); b.y = tf32_round(b.y);
        b.z = tf32_round(b.z); b.w = tf32_round(b.w);
        *(float4*)&sA[0][row * LDA + lkq * 4] = a;
        *(float4*)&sB[0][row * LDA + lkq * 4] = b;
    }
    __syncthreads();

    const int NCH = D_MODEL / BK;
    for (int c = 0; c < NCH; c++) {
        const int p = c & 1;
        if (c + 1 < NCH) {
            const int koff = (c + 1) * BK;
            #pragma unroll
            for (int j = 0; j < 2; j++) {
                ra[j] = *(const float4*)(Xb + (size_t)(lrow + j * 64) * D_MODEL + koff + lkq * 4);
                rb[j] = *(const float4*)(Wb + (size_t)(lrow + j * 64) * D_MODEL + koff + lkq * 4);
            }
        }

        const uint32_t aS = sA_u + (uint32_t)(p * STAGEF) * 4u;
        const uint32_t bS = sB_u + (uint32_t)(p * STAGEF) * 4u;
        #pragma unroll
        for (int ks = 0; ks < 2; ks++) {
            uint32_t af[4][4], bf[2][4];
            #pragma unroll
            for (int mf = 0; mf < 4; mf++)
                ldsm4(af[mf], aS + (uint32_t)(((arow + mf * 16) * LDA) + ks * 8 + acol) * 4u);
            #pragma unroll
            for (int nfp = 0; nfp < 2; nfp++)
                ldsm4(bf[nfp], bS + (uint32_t)(((brow + nfp * 16) * LDA) + ks * 8 + bcol) * 4u);
            #pragma unroll
            for (int mf = 0; mf < 4; mf++) {
                #pragma unroll
                for (int nfp = 0; nfp < 2; nfp++) {
                    mma_tf32(cacc[mf][2 * nfp],     af[mf], &bf[nfp][0]);
                    mma_tf32(cacc[mf][2 * nfp + 1], af[mf], &bf[nfp][2]);
                }
            }
        }

        if (c + 1 < NCH) {
            const int q = p ^ 1;
            #pragma unroll
            for (int j = 0; j < 2; j++) {
                const int row = lrow + j * 64;
                float4 a = ra[j], b = rb[j];
                a.x = tf32_round(a.x); a.y = tf32_round(a.y);
                a.z = tf32_round(a.z); a.w = tf32_round(a.w);
                b.x = tf32_round(b.x); b.y = tf32_round(b.y);
                b.z = tf32_round(b.z); b.w = tf32_round(b.w);
                *(float4*)&sA[q][row * LDA + lkq * 4] = a;
                *(float4*)&sB[q][row * LDA + lkq * 4] = b;
            }
            __syncthreads();
        }
    }

    #pragma unroll
    for (int mf = 0; mf < 4; mf++) {
        #pragma unroll
        for (int nf = 0; nf < 4; nf++) {
            const int m = m0 + wm * 64 + mf * 16 + g;
            const int n = n0 + wn * 32 + nf * 8 + 2 * t;
            float2 bb = *(const float2*)&bias[n];
            float2 r0, r1;
            r0.x = cacc[mf][nf][0] + bb.x;
            r0.y = cacc[mf][nf][1] + bb.y;
            r1.x = cacc[mf][nf][2] + bb.x;
            r1.y = cacc[mf][nf][3] + bb.y;
            if (HEAD_SPLIT) {
                const int h  = n >> 6;
                const int dd = n & 63;
                const int b1 = m >> 11;
                const int s1 = m & (SEQ - 1);
                *(float2*)&Y[((size_t)(b1 * N_HEADS + h) * SEQ + s1) * DEPTH + dd] = r0;
                const int m2 = m + 8;
                const int b2 = m2 >> 11;
                const int s2 = m2 & (SEQ - 1);
                *(float2*)&Y[((size_t)(b2 * N_HEADS + h) * SEQ + s2) * DEPTH + dd] = r1;
            } else {
                *(float2*)&Y[(size_t)m * D_MODEL + n] = r0;
                *(float2*)&Y[(size_t)(m + 8) * D_MODEL + n] = r1;
            }
        }
    }
}

// ---------------------------------------------------------------------------
// Flash attention via mma.sync tf32 + ldmatrix fragment feeds.
// 8 warps; warp w owns q-rows [16w, 16w+16). BQ=128, BKV=64.
// qp_s [128][68]: Q (preloaded to frags) then reused as P staging.
// k_s  [64][68]:  K rows=key, cols=d (B-frags via ldmatrix directly).
// v_t  [64][68]:  V transposed rows=d, cols=key (B-frags via ldmatrix).
// LD=68 floats = 17x16B rows (odd) -> conflict-free ldmatrix.
// ---------------------------------------------------------------------------
#define LDF 68
#define FL_SMEM ((128 + 64 + 64) * LDF * 4)   // 69632 B

__global__ __launch_bounds__(256, 2)
void flash_mma_kernel()
{
    extern __shared__ float sm[];
    float* qp_s = sm;                   // [128][LDF]
    float* k_s  = qp_s + 128 * LDF;     // [64][LDF]
    float* v_t  = k_s + 64 * LDF;       // [64][LDF]

    const int tid  = threadIdx.x;
    const int lane = tid & 31;
    const int w    = tid >> 5;
    const int g    = lane >> 2;
    const int t    = lane & 3;

    const int q0 = blockIdx.x * 128;
    const int bh = blockIdx.y;
    const int b  = bh >> 4;
    const int h  = bh & 15;

    const float scale = 0.125f;

    const float* gq = g_q + ((size_t)bh * SEQ + q0) * DEPTH;
    const float* gk = g_k + (size_t)bh * SEQ * DEPTH;
    const float* gv = g_v + (size_t)bh * SEQ * DEPTH;

    // Load Q tile (scaled + tf32-rounded)
    #pragma unroll
    for (int i = 0; i < 8; i++) {
        int id   = tid + i * 256;
        int row  = id >> 4;
        int col4 = id & 15;
        float4 v = *(const float4*)&gq[row * DEPTH + col4 * 4];
        v.x = tf32_round(v.x * scale);
        v.y = tf32_round(v.y * scale);
        v.z = tf32_round(v.z * scale);
        v.w = tf32_round(v.w * scale);
        *(float4*)&qp_s[row * LDF + col4 * 4] = v;
    }
    __syncthreads();

    // ldmatrix address bases
    const uint32_t qp_u = smem_u32(qp_s);
    const uint32_t k_u  = smem_u32(k_s);
    const uint32_t v_u  = smem_u32(v_t);
    // A-frag (Q then P): rows w*16 + (lane&15), col block +4 for lanes>=16
    const uint32_t a_addr = qp_u
        + (uint32_t)(((w * 16 + (lane & 15)) * LDF) + ((lane & 16) ? 4 : 0)) * 4u;
    // B-frag row/col pattern (shared by K and V_t)
    const int brow = ((lane & 16) ? 8 : 0) + (lane & 7);
    const int bcol = (lane & 8) ? 4 : 0;
    uint32_t kb_addr[4], vb_addr[4];
    #pragma unroll
    for (int nfp = 0; nfp < 4; nfp++) {
        kb_addr[nfp] = k_u + (uint32_t)(((nfp * 16 + brow) * LDF) + bcol) * 4u;
        vb_addr[nfp] = v_u + (uint32_t)(((nfp * 16 + brow) * LDF) + bcol) * 4u;
    }

    // Preload Q A-frags for all 8 k-steps; qp_s then free for P
    const int mr0 = w * 16 + g;
    const int mr1 = mr0 + 8;
    uint32_t qf[8][4];
    #pragma unroll
    for (int ks = 0; ks < 8; ks++) ldsm4(qf[ks], a_addr + ks * 32u);

    float of[8][4];
    #pragma unroll
    for (int nf = 0; nf < 8; nf++)
        #pragma unroll
        for (int r = 0; r < 4; r++) of[nf][r] = 0.0f;
    float m0r = -INFINITY, m1r = -INFINITY;
    float l0r = 0.0f, l1r = 0.0f;

    for (int jc = 0; jc < SEQ / 64; jc++) {
        __syncthreads();   // prior PV frag reads done before K/V overwrite

        const float* kp = gk + (size_t)jc * 64 * DEPTH;
        const float* vp = gv + (size_t)jc * 64 * DEPTH;
        // K direct copy (rounded)
        #pragma unroll
        for (int i = 0; i < 4; i++) {
            int id   = tid + i * 256;
            int row  = id >> 4;
            int col4 = id & 15;
            float4 kv4 = *(const float4*)&kp[row * DEPTH + col4 * 4];
            kv4.x = tf32_round(kv4.x); kv4.y = tf32_round(kv4.y);
            kv4.z = tf32_round(kv4.z); kv4.w = tf32_round(kv4.w);
            *(float4*)&k_s[row * LDF + col4 * 4] = kv4;
        }
        // V transposed (rounded): v_t[d][key]
        #pragma unroll
        for (int i = 0; i < 4; i++) {
            int id  = tid + i * 256;
            int key = id & 63;
            int d4  = id >> 6;
            float4 vv4 = *(const float4*)&vp[key * DEPTH + d4 * 4];
            v_t[(d4 * 4 + 0) * LDF + key] = tf32_round(vv4.x);
            v_t[(d4 * 4 + 1) * LDF + key] = tf32_round(vv4.y);
            v_t[(d4 * 4 + 2) * LDF + key] = tf32_round(vv4.z);
            v_t[(d4 * 4 + 3) * LDF + key] = tf32_round(vv4.w);
        }
        __syncthreads();

        // QK: S[16x64] per warp, 8 k-steps, B-frags via ldmatrix
        float sf[8][4];
        #pragma unroll
        for (int nf = 0; nf < 8; nf++)
            #pragma unroll
            for (int r = 0; r < 4; r++) sf[nf][r] = 0.0f;

        #pragma unroll
        for (int ks = 0; ks < 8; ks++) {
            #pragma unroll
            for (int nfp = 0; nfp < 4; nfp++) {
                uint32_t bf[4];
                ldsm4(bf, kb_addr[nfp] + ks * 32u);
                mma_tf32(sf[2 * nfp],     qf[ks], &bf[0]);
                mma_tf32(sf[2 * nfp + 1], qf[ks], &bf[2]);
            }
        }

        // Online softmax on fragments (rows mr0: c0,c1; mr1: c2,c3)
        float mx0 = -INFINITY, mx1 = -INFINITY;
        #pragma unroll
        for (int nf = 0; nf < 8; nf++) {
            mx0 = fmaxf(mx0, fmaxf(sf[nf][0], sf[nf][1]));
            mx1 = fmaxf(mx1, fmaxf(sf[nf][2], sf[nf][3]));
        }
        mx0 = fmaxf(mx0, __shfl_xor_sync(0xffffffffu, mx0, 1));
        mx0 = fmaxf(mx0, __shfl_xor_sync(0xffffffffu, mx0, 2));
        mx1 = fmaxf(mx1, __shfl_xor_sync(0xffffffffu, mx1, 1));
        mx1 = fmaxf(mx1, __shfl_xor_sync(0xffffffffu, mx1, 2));

        const float mn0 = fmaxf(m0r, mx0);
        const float mn1 = fmaxf(m1r, mx1);
        const float al0 = __expf(m0r - mn0);
        const float al1 = __expf(m1r - mn1);
        m0r = mn0; m1r = mn1;

        float rs0 = 0.0f, rs1 = 0.0f;
        #pragma unroll
        for (int nf = 0; nf < 8; nf++) {
            sf[nf][0] = tf32_round(__expf(sf[nf][0] - mn0));
            sf[nf][1] = tf32_round(__expf(sf[nf][1] - mn0));
            sf[nf][2] = tf32_round(__expf(sf[nf][2] - mn1));
            sf[nf][3] = tf32_round(__expf(sf[nf][3] - mn1));
            rs0 += sf[nf][0] + sf[nf][1];
            rs1 += sf[nf][2] + sf[nf][3];
        }
        rs0 += __shfl_xor_sync(0xffffffffu, rs0, 1);
        rs0 += __shfl_xor_sync(0xffffffffu, rs0, 2);
        rs1 += __shfl_xor_sync(0xffffffffu, rs1, 1);
        rs1 += __shfl_xor_sync(0xffffffffu, rs1, 2);
        l0r = l0r * al0 + rs0;
        l1r = l1r * al1 + rs1;

        #pragma unroll
        for (int nf = 0; nf < 8; nf++) {
            of[nf][0] *= al0; of[nf][1] *= al0;
            of[nf][2] *= al1; of[nf][3] *= al1;
        }

        // Stage P (warp-private rows) into qp_s
        #pragma unroll
        for (int nf = 0; nf < 8; nf++) {
            *(float2*)&qp_s[mr0 * LDF + nf * 8 + 2 * t] = make_float2(sf[nf][0], sf[nf][1]);
            *(float2*)&qp_s[mr1 * LDF + nf * 8 + 2 * t] = make_float2(sf[nf][2], sf[nf][3]);
        }
        __syncwarp();

        // PV: O += P @ V, A- and B-frags via ldmatrix
        #pragma unroll
        for (int ks = 0; ks < 8; ks++) {
            uint32_t pf[4];
            ldsm4(pf, a_addr + ks * 32u);
            #pragma unroll
            for (int nfp = 0; nfp < 4; nfp++) {
                uint32_t bf[4];
                ldsm4(bf, vb_addr[nfp] + ks * 32u);
                mma_tf32(of[2 * nfp],     pf, &bf[0]);
                mma_tf32(of[2 * nfp + 1], pf, &bf[2]);
            }
        }
    }

    // Epilogue: normalize, write [B,S,D] with heads re-interleaved
    const float inv0 = 1.0f / l0r;
    const float inv1 = 1.0f / l1r;
    const size_t r0base = (size_t)(b * SEQ + q0 + mr0) * D_MODEL + h * DEPTH;
    const size_t r1base = (size_t)(b * SEQ + q0 + mr1) * D_MODEL + h * DEPTH;
    #pragma unroll
    for (int nf = 0; nf < 8; nf++) {
        const int col = nf * 8 + 2 * t;
        *(float2*)&g_ao[r0base + col] = make_float2(of[nf][0] * inv0, of[nf][1] * inv0);
        *(float2*)&g_ao[r1base + col] = make_float2(of[nf][2] * inv1, of[nf][3] * inv1);
    }
}

// ---------------------------------------------------------------------------
// Launch
// ---------------------------------------------------------------------------
extern "C" void kernel_launch(void* const* d_in, const int* in_sizes, int n_in,
                              void* d_out, int out_size)
{
    const float* Q  = (const float*)d_in[0];
    const float* K  = (const float*)d_in[1];
    const float* V  = (const float*)d_in[2];
    const float* Wq = (const float*)d_in[3];
    const float* bq = (const float*)d_in[4];
    const float* Wk = (const float*)d_in[5];
    const float* bk = (const float*)d_in[6];
    const float* Wv = (const float*)d_in[7];
    const float* bv = (const float*)d_in[8];
    const float* Wo = (const float*)d_in[9];
    const float* bo = (const float*)d_in[10];
    float* out = (float*)d_out;

    float *gq, *gk, *gv, *gao;
    cudaGetSymbolAddress((void**)&gq,  g_q);
    cudaGetSymbolAddress((void**)&gk,  g_k);
    cudaGetSymbolAddress((void**)&gv,  g_v);
    cudaGetSymbolAddress((void**)&gao, g_ao);

    static bool attr_set = false;
    if (!attr_set) {
        cudaFuncSetAttribute(flash_mma_kernel,
                             cudaFuncAttributeMaxDynamicSharedMemorySize, FL_SMEM);
        attr_set = true;
    }

    const dim3 ggrid(D_MODEL / 128, M_TOT / 128);   // (8, 32)

    gemm_mma_kernel<1><<<ggrid, 256>>>(Q, Wq, bq, gq);
    gemm_mma_kernel<1><<<ggrid, 256>>>(K, Wk, bk, gk);
    gemm_mma_kernel<1><<<ggrid, 256>>>(V, Wv, bv, gv);

    flash_mma_kernel<<<dim3(SEQ / 128, BATCH * N_HEADS), 256, FL_SMEM>>>();

    gemm_mma_kernel<0><<<ggrid, 256>>>(gao, Wo, bo, out);
}

// round 8
// speedup vs baseline: 1.0522x; 1.0522x over previous
#include <cuda_runtime.h>
#include <math.h>
#include <stdint.h>

#define D_MODEL 1024
#define N_HEADS 16
#define DEPTH   64
#define BATCH   2
#define SEQ     2048
#define M_TOT   (BATCH * SEQ)   // 4096

// ---------------------------------------------------------------------------
// Scratch (no cudaMalloc allowed): device globals
// g_q/g_k/g_v hold tf32-rounded values (g_q additionally pre-scaled by 0.125)
// ---------------------------------------------------------------------------
__device__ float g_q[BATCH * N_HEADS * SEQ * DEPTH];   // [B,H,S,64]
__device__ float g_k[BATCH * N_HEADS * SEQ * DEPTH];
__device__ float g_v[BATCH * N_HEADS * SEQ * DEPTH];
__device__ float g_ao[M_TOT * D_MODEL];                // attention out [B,S,D]

// ---------------------------------------------------------------------------
// PTX helpers (baseline features only — legal on sm_103 target)
// ---------------------------------------------------------------------------
__device__ __forceinline__ void mma_tf32(float c[4], const uint32_t a[4],
                                         const uint32_t b[2]) {
    asm volatile(
        "mma.sync.aligned.m16n8k8.row.col.f32.tf32.tf32.f32 "
        "{%0,%1,%2,%3}, {%4,%5,%6,%7}, {%8,%9}, {%0,%1,%2,%3};\n"
        : "+f"(c[0]), "+f"(c[1]), "+f"(c[2]), "+f"(c[3])
        : "r"(a[0]), "r"(a[1]), "r"(a[2]), "r"(a[3]),
          "r"(b[0]), "r"(b[1]));
}

__device__ __forceinline__ void ldsm4(uint32_t r[4], uint32_t addr) {
    asm volatile("ldmatrix.sync.aligned.m8n8.x4.shared.b16 {%0,%1,%2,%3}, [%4];"
        : "=r"(r[0]), "=r"(r[1]), "=r"(r[2]), "=r"(r[3]) : "r"(addr));
}

__device__ __forceinline__ uint32_t smem_u32(const void* p) {
    uint32_t a;
    asm("{ .reg .u64 t; cvta.to.shared.u64 t, %1; cvt.u32.u64 %0, t; }"
        : "=r"(a) : "l"(p));
    return a;
}

__device__ __forceinline__ float tf32_round(float x) {
    uint32_t t;
    asm("cvt.rna.tf32.f32 %0, %1;" : "=r"(t) : "f"(x));
    return __uint_as_float(t);
}

__device__ __forceinline__ void cp16(uint32_t dst, const void* src) {
    asm volatile("cp.async.ca.shared.global [%0], [%1], 16;"
                 :: "r"(dst), "l"(src) : "memory");
}
#define CP_COMMIT() asm volatile("cp.async.commit_group;" ::: "memory")
#define CP_WAIT(n)  asm volatile("cp.async.wait_group %0;" :: "n"(n) : "memory")

// ---------------------------------------------------------------------------
// GEMM (tensor-core tf32): Y = X @ W^T + bias
// Block 128x128, BK=16, double-buffered smem, 8 warps (2m x 4n), warp 64x32.
// Fragments via ldmatrix.x4 (LDA=20 floats -> odd 16B row stride).
// HEAD_SPLIT epilogue rounds result to tf32 and applies oscale (exact for
// powers of two), so the attention kernel consumes ready-to-MMA values.
// ---------------------------------------------------------------------------
#define BK   16
#define LDA  20
#define STAGEF (128 * LDA)

template <int HEAD_SPLIT>
__global__ __launch_bounds__(256, 2)
void gemm_mma_kernel(const float* __restrict__ X,
                     const float* __restrict__ W,
                     const float* __restrict__ bias,
                     float* __restrict__ Y,
                     float oscale)
{
    __shared__ float sA[2][STAGEF];
    __shared__ float sB[2][STAGEF];

    const int tid  = threadIdx.x;
    const int lane = tid & 31;
    const int wid  = tid >> 5;
    const int wm   = wid & 1;
    const int wn   = wid >> 1;
    const int g    = lane >> 2;
    const int t    = lane & 3;
    const int m0   = blockIdx.y * 128;
    const int n0   = blockIdx.x * 128;

    const int lrow = tid >> 2;
    const int lkq  = tid & 3;

    const int arow = wm * 64 + (lane & 15);
    const int acol = (lane & 16) ? 4 : 0;
    const int brow = wn * 32 + ((lane & 16) ? 8 : 0) + (lane & 7);
    const int bcol = (lane & 8) ? 4 : 0;
    const uint32_t sA_u = smem_u32(sA);
    const uint32_t sB_u = smem_u32(sB);

    float cacc[4][4][4];
    #pragma unroll
    for (int mf = 0; mf < 4; mf++)
        #pragma unroll
        for (int nf = 0; nf < 4; nf++)
            #pragma unroll
            for (int r = 0; r < 4; r++) cacc[mf][nf][r] = 0.0f;

    const float* Xb = X + (size_t)m0 * D_MODEL;
    const float* Wb = W + (size_t)n0 * D_MODEL;

    float4 ra[2], rb[2];

    #pragma unroll
    for (int j = 0; j < 2; j++) {
        ra[j] = *(const float4*)(Xb + (size_t)(lrow + j * 64) * D_MODEL + lkq * 4);
        rb[j] = *(const float4*)(Wb + (size_t)(lrow + j * 64) * D_MODEL + lkq * 4);
    }
    #pragma unroll
    for (int j = 0; j < 2; j++) {
        const int row = lrow + j * 64;
        float4 a = ra[j], b = rb[j];
        a.x = tf32_round(a.x); a.y = tf32_round(a.y);
        a.z = tf32_round(a.z); a.w = tf32_round(a.w);
        b.x = tf32_round(b.x); b.y = tf32_round(b.y);
        b.z = tf32_round(b.z); b.w = tf32_round(b.w);
        *(float4*)&sA[0][row * LDA + lkq * 4] = a;
        *(float4*)&sB[0][row * LDA + lkq * 4] = b;
    }
    __syncthreads();

    const int NCH = D_MODEL / BK;
    for (int c = 0; c < NCH; c++) {
        const int p = c & 1;
        if (c + 1 < NCH) {
            const int koff = (c + 1) * BK;
            #pragma unroll
            for (int j = 0; j < 2; j++) {
                ra[j] = *(const float4*)(Xb + (size_t)(lrow + j * 64) * D_MODEL + koff + lkq * 4);
                rb[j] = *(const float4*)(Wb + (size_t)(lrow + j * 64) * D_MODEL + koff + lkq * 4);
            }
        }

        const uint32_t aS = sA_u + (uint32_t)(p * STAGEF) * 4u;
        const uint32_t bS = sB_u + (uint32_t)(p * STAGEF) * 4u;
        #pragma unroll
        for (int ks = 0; ks < 2; ks++) {
            uint32_t af[4][4], bf[2][4];
            #pragma unroll
            for (int mf = 0; mf < 4; mf++)
                ldsm4(af[mf], aS + (uint32_t)(((arow + mf * 16) * LDA) + ks * 8 + acol) * 4u);
            #pragma unroll
            for (int nfp = 0; nfp < 2; nfp++)
                ldsm4(bf[nfp], bS + (uint32_t)(((brow + nfp * 16) * LDA) + ks * 8 + bcol) * 4u);
            #pragma unroll
            for (int mf = 0; mf < 4; mf++) {
                #pragma unroll
                for (int nfp = 0; nfp < 2; nfp++) {
                    mma_tf32(cacc[mf][2 * nfp],     af[mf], &bf[nfp][0]);
                    mma_tf32(cacc[mf][2 * nfp + 1], af[mf], &bf[nfp][2]);
                }
            }
        }

        if (c + 1 < NCH) {
            const int q = p ^ 1;
            #pragma unroll
            for (int j = 0; j < 2; j++) {
                const int row = lrow + j * 64;
                float4 a = ra[j], b = rb[j];
                a.x = tf32_round(a.x); a.y = tf32_round(a.y);
                a.z = tf32_round(a.z); a.w = tf32_round(a.w);
                b.x = tf32_round(b.x); b.y = tf32_round(b.y);
                b.z = tf32_round(b.z); b.w = tf32_round(b.w);
                *(float4*)&sA[q][row * LDA + lkq * 4] = a;
                *(float4*)&sB[q][row * LDA + lkq * 4] = b;
            }
            __syncthreads();
        }
    }

    #pragma unroll
    for (int mf = 0; mf < 4; mf++) {
        #pragma unroll
        for (int nf = 0; nf < 4; nf++) {
            const int m = m0 + wm * 64 + mf * 16 + g;
            const int n = n0 + wn * 32 + nf * 8 + 2 * t;
            float2 bb = *(const float2*)&bias[n];
            float2 r0, r1;
            r0.x = cacc[mf][nf][0] + bb.x;
            r0.y = cacc[mf][nf][1] + bb.y;
            r1.x = cacc[mf][nf][2] + bb.x;
            r1.y = cacc[mf][nf][3] + bb.y;
            if (HEAD_SPLIT) {
                // tf32-round + exact scale so flash consumes ready values
                r0.x = tf32_round(r0.x) * oscale;
                r0.y = tf32_round(r0.y) * oscale;
                r1.x = tf32_round(r1.x) * oscale;
                r1.y = tf32_round(r1.y) * oscale;
                const int h  = n >> 6;
                const int dd = n & 63;
                const int b1 = m >> 11;
                const int s1 = m & (SEQ - 1);
                *(float2*)&Y[((size_t)(b1 * N_HEADS + h) * SEQ + s1) * DEPTH + dd] = r0;
                const int m2 = m + 8;
                const int b2 = m2 >> 11;
                const int s2 = m2 & (SEQ - 1);
                *(float2*)&Y[((size_t)(b2 * N_HEADS + h) * SEQ + s2) * DEPTH + dd] = r1;
            } else {
                *(float2*)&Y[(size_t)m * D_MODEL + n] = r0;
                *(float2*)&Y[(size_t)(m + 8) * D_MODEL + n] = r1;
            }
        }
    }
}

// ---------------------------------------------------------------------------
// Flash attention: mma.sync tf32, scalar-LDS fragment feeds (R6 pattern),
// cp.async 2-stage ping-pong for K/V (inputs pre-rounded by GEMM epilogue).
// 8 warps; warp w owns q-rows [16w,16w+16). BQ=128, BKV=64.
// qp_s [128][68]: Q (frag-preloaded) then reused as P staging.
// k_s: 2 stages [64][68] (rows=key, cols=d).
// v_s: 2 stages [64][72] row-major (bank 8t+g permutation for B-feed).
// ---------------------------------------------------------------------------
#define LDK 68
#define LDV 72
#define KSTG (64 * LDK)
#define VSTG (64 * LDV)
#define FL_SMEM ((128 * LDK + 2 * KSTG + 2 * VSTG) * 4)   // 106496 B

__global__ __launch_bounds__(256, 2)
void flash_mma_kernel()
{
    extern __shared__ float sm[];
    float* qp_s = sm;                    // [128][LDK]
    float* k_s  = qp_s + 128 * LDK;      // 2 x [64][LDK]
    float* v_s  = k_s + 2 * KSTG;        // 2 x [64][LDV]

    const int tid  = threadIdx.x;
    const int lane = tid & 31;
    const int w    = tid >> 5;
    const int g    = lane >> 2;
    const int t    = lane & 3;

    const int q0 = blockIdx.x * 128;
    const int bh = blockIdx.y;
    const int b  = bh >> 4;
    const int h  = bh & 15;

    const float* gq = g_q + ((size_t)bh * SEQ + q0) * DEPTH;
    const float* gk = g_k + (size_t)bh * SEQ * DEPTH;
    const float* gv = g_v + (size_t)bh * SEQ * DEPTH;

    const uint32_t k_u = smem_u32(k_s);
    const uint32_t v_u = smem_u32(v_s);

    // Per-thread copy coords (64 rows x 16 float4, 4 per thread)
    const int crow = tid >> 4;    // 0..15, +16 per i
    const int ccol = tid & 15;

    // Prefetch chunk 0 into stage 0 ASAP
    {
        #pragma unroll
        for (int i = 0; i < 4; i++) {
            const int row = crow + i * 16;
            cp16(k_u + (uint32_t)(row * LDK + ccol * 4) * 4u,
                 gk + row * DEPTH + ccol * 4);
            cp16(v_u + (uint32_t)(row * LDV + ccol * 4) * 4u,
                 gv + row * DEPTH + ccol * 4);
        }
        CP_COMMIT();
    }

    // Load Q tile (already rounded+scaled by GEMM epilogue)
    #pragma unroll
    for (int i = 0; i < 8; i++) {
        int id   = tid + i * 256;
        int row  = id >> 4;
        int col4 = id & 15;
        *(float4*)&qp_s[row * LDK + col4 * 4] =
            *(const float4*)&gq[row * DEPTH + col4 * 4];
    }
    __syncthreads();

    // Preload Q A-frags for all 8 k-steps; qp_s then free for P
    const int mr0 = w * 16 + g;
    const int mr1 = mr0 + 8;
    uint32_t qf[8][4];
    #pragma unroll
    for (int ks = 0; ks < 8; ks++) {
        qf[ks][0] = __float_as_uint(qp_s[mr0 * LDK + t + ks * 8]);
        qf[ks][1] = __float_as_uint(qp_s[mr1 * LDK + t + ks * 8]);
        qf[ks][2] = __float_as_uint(qp_s[mr0 * LDK + t + 4 + ks * 8]);
        qf[ks][3] = __float_as_uint(qp_s[mr1 * LDK + t + 4 + ks * 8]);
    }

    float of[8][4];
    #pragma unroll
    for (int nf = 0; nf < 8; nf++)
        #pragma unroll
        for (int r = 0; r < 4; r++) of[nf][r] = 0.0f;
    float m0r = -INFINITY, m1r = -INFINITY;
    float l0r = 0.0f, l1r = 0.0f;

    const int NCHK = SEQ / 64;   // 32
    for (int jc = 0; jc < NCHK; jc++) {
        const int p = jc & 1;

        // Prefetch next chunk into the other stage
        if (jc + 1 < NCHK) {
            const float* kp = gk + (size_t)(jc + 1) * 64 * DEPTH;
            const float* vp = gv + (size_t)(jc + 1) * 64 * DEPTH;
            const uint32_t kd = k_u + (uint32_t)((p ^ 1) * KSTG) * 4u;
            const uint32_t vd = v_u + (uint32_t)((p ^ 1) * VSTG) * 4u;
            #pragma unroll
            for (int i = 0; i < 4; i++) {
                const int row = crow + i * 16;
                cp16(kd + (uint32_t)(row * LDK + ccol * 4) * 4u,
                     kp + row * DEPTH + ccol * 4);
                cp16(vd + (uint32_t)(row * LDV + ccol * 4) * 4u,
                     vp + row * DEPTH + ccol * 4);
            }
            CP_COMMIT();
            CP_WAIT(1);
        } else {
            CP_WAIT(0);
        }
        __syncthreads();

        const float* kS = k_s + p * KSTG;
        const float* vS = v_s + p * VSTG;

        // QK: S[16x64] per warp, 8 k-steps (scalar LDS broadcast feeds)
        float sf[8][4];
        #pragma unroll
        for (int nf = 0; nf < 8; nf++)
            #pragma unroll
            for (int r = 0; r < 4; r++) sf[nf][r] = 0.0f;

        #pragma unroll
        for (int ks = 0; ks < 8; ks++) {
            #pragma unroll
            for (int nf = 0; nf < 8; nf++) {
                uint32_t bf[2];
                bf[0] = __float_as_uint(kS[(g + nf * 8) * LDK + t + ks * 8]);
                bf[1] = __float_as_uint(kS[(g + nf * 8) * LDK + t + 4 + ks * 8]);
                mma_tf32(sf[nf], qf[ks], bf);
            }
        }

        // Online softmax on fragments (rows mr0: c0,c1; mr1: c2,c3)
        float mx0 = -INFINITY, mx1 = -INFINITY;
        #pragma unroll
        for (int nf = 0; nf < 8; nf++) {
            mx0 = fmaxf(mx0, fmaxf(sf[nf][0], sf[nf][1]));
            mx1 = fmaxf(mx1, fmaxf(sf[nf][2], sf[nf][3]));
        }
        mx0 = fmaxf(mx0, __shfl_xor_sync(0xffffffffu, mx0, 1));
        mx0 = fmaxf(mx0, __shfl_xor_sync(0xffffffffu, mx0, 2));
        mx1 = fmaxf(mx1, __shfl_xor_sync(0xffffffffu, mx1, 1));
        mx1 = fmaxf(mx1, __shfl_xor_sync(0xffffffffu, mx1, 2));

        const float mn0 = fmaxf(m0r, mx0);
        const float mn1 = fmaxf(m1r, mx1);
        const float al0 = __expf(m0r - mn0);
        const float al1 = __expf(m1r - mn1);
        m0r = mn0; m1r = mn1;

        float rs0 = 0.0f, rs1 = 0.0f;
        #pragma unroll
        for (int nf = 0; nf < 8; nf++) {
            sf[nf][0] = tf32_round(__expf(sf[nf][0] - mn0));
            sf[nf][1] = tf32_round(__expf(sf[nf][1] - mn0));
            sf[nf][2] = tf32_round(__expf(sf[nf][2] - mn1));
            sf[nf][3] = tf32_round(__expf(sf[nf][3] - mn1));
            rs0 += sf[nf][0] + sf[nf][1];
            rs1 += sf[nf][2] + sf[nf][3];
        }
        rs0 += __shfl_xor_sync(0xffffffffu, rs0, 1);
        rs0 += __shfl_xor_sync(0xffffffffu, rs0, 2);
        rs1 += __shfl_xor_sync(0xffffffffu, rs1, 1);
        rs1 += __shfl_xor_sync(0xffffffffu, rs1, 2);
        l0r = l0r * al0 + rs0;
        l1r = l1r * al1 + rs1;

        #pragma unroll
        for (int nf = 0; nf < 8; nf++) {
            of[nf][0] *= al0; of[nf][1] *= al0;
            of[nf][2] *= al1; of[nf][3] *= al1;
        }

        // Stage P (warp-private rows) into qp_s
        #pragma unroll
        for (int nf = 0; nf < 8; nf++) {
            *(float2*)&qp_s[mr0 * LDK + nf * 8 + 2 * t] = make_float2(sf[nf][0], sf[nf][1]);
            *(float2*)&qp_s[mr1 * LDK + nf * 8 + 2 * t] = make_float2(sf[nf][2], sf[nf][3]);
        }
        __syncwarp();

        // PV: O += P @ V
        #pragma unroll
        for (int ks = 0; ks < 8; ks++) {
            uint32_t af[4];
            af[0] = __float_as_uint(qp_s[mr0 * LDK + t + ks * 8]);
            af[1] = __float_as_uint(qp_s[mr1 * LDK + t + ks * 8]);
            af[2] = __float_as_uint(qp_s[mr0 * LDK + t + 4 + ks * 8]);
            af[3] = __float_as_uint(qp_s[mr1 * LDK + t + 4 + ks * 8]);
            #pragma unroll
            for (int nf = 0; nf < 8; nf++) {
                uint32_t bf[2];
                bf[0] = __float_as_uint(vS[(t + ks * 8) * LDV + g + nf * 8]);
                bf[1] = __float_as_uint(vS[(t + 4 + ks * 8) * LDV + g + nf * 8]);
                mma_tf32(of[nf], af, bf);
            }
        }
        __syncthreads();   // all reads of stage p done before it is refilled
    }

    // Epilogue: normalize, write [B,S,D] with heads re-interleaved
    const float inv0 = 1.0f / l0r;
    const float inv1 = 1.0f / l1r;
    const size_t r0base = (size_t)(b * SEQ + q0 + mr0) * D_MODEL + h * DEPTH;
    const size_t r1base = (size_t)(b * SEQ + q0 + mr1) * D_MODEL + h * DEPTH;
    #pragma unroll
    for (int nf = 0; nf < 8; nf++) {
        const int col = nf * 8 + 2 * t;
        *(float2*)&g_ao[r0base + col] = make_float2(of[nf][0] * inv0, of[nf][1] * inv0);
        *(float2*)&g_ao[r1base + col] = make_float2(of[nf][2] * inv1, of[nf][3] * inv1);
    }
}

// ---------------------------------------------------------------------------
// Launch
// ---------------------------------------------------------------------------
extern "C" void kernel_launch(void* const* d_in, const int* in_sizes, int n_in,
                              void* d_out, int out_size)
{
    const float* Q  = (const float*)d_in[0];
    const float* K  = (const float*)d_in[1];
    const float* V  = (const float*)d_in[2];
    const float* Wq = (const float*)d_in[3];
    const float* bq = (const float*)d_in[4];
    const float* Wk = (const float*)d_in[5];
    const float* bk = (const float*)d_in[6];
    const float* Wv = (const float*)d_in[7];
    const float* bv = (const float*)d_in[8];
    const float* Wo = (const float*)d_in[9];
    const float* bo = (const float*)d_in[10];
    float* out = (float*)d_out;

    float *gq, *gk, *gv, *gao;
    cudaGetSymbolAddress((void**)&gq,  g_q);
    cudaGetSymbolAddress((void**)&gk,  g_k);
    cudaGetSymbolAddress((void**)&gv,  g_v);
    cudaGetSymbolAddress((void**)&gao, g_ao);

    static bool attr_set = false;
    if (!attr_set) {
        cudaFuncSetAttribute(flash_mma_kernel,
                             cudaFuncAttributeMaxDynamicSharedMemorySize, FL_SMEM);
        attr_set = true;
    }

    const dim3 ggrid(D_MODEL / 128, M_TOT / 128);   // (8, 32)

    // Projections: outputs tf32-rounded; Q additionally pre-scaled by 1/8
    gemm_mma_kernel<1><<<ggrid, 256>>>(Q, Wq, bq, gq, 0.125f);
    gemm_mma_kernel<1><<<ggrid, 256>>>(K, Wk, bk, gk, 1.0f);
    gemm_mma_kernel<1><<<ggrid, 256>>>(V, Wv, bv, gv, 1.0f);

    flash_mma_kernel<<<dim3(SEQ / 128, BATCH * N_HEADS), 256, FL_SMEM>>>();

    gemm_mma_kernel<0><<<ggrid, 256>>>(gao, Wo, bo, out, 1.0f);
}

// round 9
// speedup vs baseline: 1.4683x; 1.3955x over previous
#include <cuda_runtime.h>
#include <cuda_fp16.h>
#include <math.h>
#include <stdint.h>

#define D_MODEL 1024
#define N_HEADS 16
#define DEPTH   64
#define BATCH   2
#define SEQ     2048
#define M_TOT   (BATCH * SEQ)   // 4096

// ---------------------------------------------------------------------------
// Scratch (no cudaMalloc allowed): device globals
// g_q/g_k/g_v hold fp16 values (g_q pre-scaled by 0.125)
// ---------------------------------------------------------------------------
__device__ __half g_q[BATCH * N_HEADS * SEQ * DEPTH];   // [B,H,S,64]
__device__ __half g_k[BATCH * N_HEADS * SEQ * DEPTH];
__device__ __half g_v[BATCH * N_HEADS * SEQ * DEPTH];
__device__ float  g_ao[M_TOT * D_MODEL];                // attention out [B,S,D]

// ---------------------------------------------------------------------------
// PTX helpers (baseline features only — legal on sm_103 target)
// ---------------------------------------------------------------------------
__device__ __forceinline__ void mma_tf32(float c[4], const uint32_t a[4],
                                         const uint32_t b[2]) {
    asm volatile(
        "mma.sync.aligned.m16n8k8.row.col.f32.tf32.tf32.f32 "
        "{%0,%1,%2,%3}, {%4,%5,%6,%7}, {%8,%9}, {%0,%1,%2,%3};\n"
        : "+f"(c[0]), "+f"(c[1]), "+f"(c[2]), "+f"(c[3])
        : "r"(a[0]), "r"(a[1]), "r"(a[2]), "r"(a[3]),
          "r"(b[0]), "r"(b[1]));
}

__device__ __forceinline__ void mma_f16(float c[4], const uint32_t a[4],
                                        const uint32_t b[2]) {
    asm volatile(
        "mma.sync.aligned.m16n8k16.row.col.f32.f16.f16.f32 "
        "{%0,%1,%2,%3}, {%4,%5,%6,%7}, {%8,%9}, {%0,%1,%2,%3};\n"
        : "+f"(c[0]), "+f"(c[1]), "+f"(c[2]), "+f"(c[3])
        : "r"(a[0]), "r"(a[1]), "r"(a[2]), "r"(a[3]),
          "r"(b[0]), "r"(b[1]));
}

__device__ __forceinline__ void ldsm4(uint32_t r[4], uint32_t addr) {
    asm volatile("ldmatrix.sync.aligned.m8n8.x4.shared.b16 {%0,%1,%2,%3}, [%4];"
        : "=r"(r[0]), "=r"(r[1]), "=r"(r[2]), "=r"(r[3]) : "r"(addr));
}
__device__ __forceinline__ void ldsm4t(uint32_t r[4], uint32_t addr) {
    asm volatile("ldmatrix.sync.aligned.m8n8.x4.trans.shared.b16 {%0,%1,%2,%3}, [%4];"
        : "=r"(r[0]), "=r"(r[1]), "=r"(r[2]), "=r"(r[3]) : "r"(addr));
}

__device__ __forceinline__ uint32_t smem_u32(const void* p) {
    uint32_t a;
    asm("{ .reg .u64 t; cvta.to.shared.u64 t, %1; cvt.u32.u64 %0, t; }"
        : "=r"(a) : "l"(p));
    return a;
}

__device__ __forceinline__ float tf32_round(float x) {
    uint32_t t;
    asm("cvt.rna.tf32.f32 %0, %1;" : "=r"(t) : "f"(x));
    return __uint_as_float(t);
}

__device__ __forceinline__ void cp16(uint32_t dst, const void* src) {
    asm volatile("cp.async.ca.shared.global [%0], [%1], 16;"
                 :: "r"(dst), "l"(src) : "memory");
}
#define CP_COMMIT() asm volatile("cp.async.commit_group;" ::: "memory")
#define CP_WAIT(n)  asm volatile("cp.async.wait_group %0;" :: "n"(n) : "memory")

// ---------------------------------------------------------------------------
// GEMM (tensor-core tf32): Y = X @ W^T + bias. Internals unchanged (passing).
// HEAD_SPLIT=1: epilogue converts to fp16 (with oscale folded, exact for
// powers of two) and writes __half head-split layout.
// ---------------------------------------------------------------------------
#define BK   16
#define LDA  20
#define STAGEF (128 * LDA)

template <int HEAD_SPLIT>
__global__ __launch_bounds__(256, 2)
void gemm_mma_kernel(const float* __restrict__ X,
                     const float* __restrict__ W,
                     const float* __restrict__ bias,
                     void* __restrict__ Yv,
                     float oscale)
{
    __shared__ float sA[2][STAGEF];
    __shared__ float sB[2][STAGEF];

    const int tid  = threadIdx.x;
    const int lane = tid & 31;
    const int wid  = tid >> 5;
    const int wm   = wid & 1;
    const int wn   = wid >> 1;
    const int g    = lane >> 2;
    const int t    = lane & 3;
    const int m0   = blockIdx.y * 128;
    const int n0   = blockIdx.x * 128;

    const int lrow = tid >> 2;
    const int lkq  = tid & 3;

    const int arow = wm * 64 + (lane & 15);
    const int acol = (lane & 16) ? 4 : 0;
    const int brow = wn * 32 + ((lane & 16) ? 8 : 0) + (lane & 7);
    const int bcol = (lane & 8) ? 4 : 0;
    const uint32_t sA_u = smem_u32(sA);
    const uint32_t sB_u = smem_u32(sB);

    float cacc[4][4][4];
    #pragma unroll
    for (int mf = 0; mf < 4; mf++)
        #pragma unroll
        for (int nf = 0; nf < 4; nf++)
            #pragma unroll
            for (int r = 0; r < 4; r++) cacc[mf][nf][r] = 0.0f;

    const float* Xb = X + (size_t)m0 * D_MODEL;
    const float* Wb = W + (size_t)n0 * D_MODEL;

    float4 ra[2], rb[2];

    #pragma unroll
    for (int j = 0; j < 2; j++) {
        ra[j] = *(const float4*)(Xb + (size_t)(lrow + j * 64) * D_MODEL + lkq * 4);
        rb[j] = *(const float4*)(Wb + (size_t)(lrow + j * 64) * D_MODEL + lkq * 4);
    }
    #pragma unroll
    for (int j = 0; j < 2; j++) {
        const int row = lrow + j * 64;
        float4 a = ra[j], b = rb[j];
        a.x = tf32_round(a.x); a.y = tf32_round(a.y);
        a.z = tf32_round(a.z); a.w = tf32_round(a.w);
        b.x = tf32_round(b.x); b.y = tf32_round(b.y);
        b.z = tf32_round(b.z); b.w = tf32_round(b.w);
        *(float4*)&sA[0][row * LDA + lkq * 4] = a;
        *(float4*)&sB[0][row * LDA + lkq * 4] = b;
    }
    __syncthreads();

    const int NCH = D_MODEL / BK;
    for (int c = 0; c < NCH; c++) {
        const int p = c & 1;
        if (c + 1 < NCH) {
            const int koff = (c + 1) * BK;
            #pragma unroll
            for (int j = 0; j < 2; j++) {
                ra[j] = *(const float4*)(Xb + (size_t)(lrow + j * 64) * D_MODEL + koff + lkq * 4);
                rb[j] = *(const float4*)(Wb + (size_t)(lrow + j * 64) * D_MODEL + koff + lkq * 4);
            }
        }

        const uint32_t aS = sA_u + (uint32_t)(p * STAGEF) * 4u;
        const uint32_t bS = sB_u + (uint32_t)(p * STAGEF) * 4u;
        #pragma unroll
        for (int ks = 0; ks < 2; ks++) {
            uint32_t af[4][4], bf[2][4];
            #pragma unroll
            for (int mf = 0; mf < 4; mf++)
                ldsm4(af[mf], aS + (uint32_t)(((arow + mf * 16) * LDA) + ks * 8 + acol) * 4u);
            #pragma unroll
            for (int nfp = 0; nfp < 2; nfp++)
                ldsm4(bf[nfp], bS + (uint32_t)(((brow + nfp * 16) * LDA) + ks * 8 + bcol) * 4u);
            #pragma unroll
            for (int mf = 0; mf < 4; mf++) {
                #pragma unroll
                for (int nfp = 0; nfp < 2; nfp++) {
                    mma_tf32(cacc[mf][2 * nfp],     af[mf], &bf[nfp][0]);
                    mma_tf32(cacc[mf][2 * nfp + 1], af[mf], &bf[nfp][2]);
                }
            }
        }

        if (c + 1 < NCH) {
            const int q = p ^ 1;
            #pragma unroll
            for (int j = 0; j < 2; j++) {
                const int row = lrow + j * 64;
                float4 a = ra[j], b = rb[j];
                a.x = tf32_round(a.x); a.y = tf32_round(a.y);
                a.z = tf32_round(a.z); a.w = tf32_round(a.w);
                b.x = tf32_round(b.x); b.y = tf32_round(b.y);
                b.z = tf32_round(b.z); b.w = tf32_round(b.w);
                *(float4*)&sA[q][row * LDA + lkq * 4] = a;
                *(float4*)&sB[q][row * LDA + lkq * 4] = b;
            }
            __syncthreads();
        }
    }

    #pragma unroll
    for (int mf = 0; mf < 4; mf++) {
        #pragma unroll
        for (int nf = 0; nf < 4; nf++) {
            const int m = m0 + wm * 64 + mf * 16 + g;
            const int n = n0 + wn * 32 + nf * 8 + 2 * t;
            float2 bb = *(const float2*)&bias[n];
            float2 r0, r1;
            r0.x = cacc[mf][nf][0] + bb.x;
            r0.y = cacc[mf][nf][1] + bb.y;
            r1.x = cacc[mf][nf][2] + bb.x;
            r1.y = cacc[mf][nf][3] + bb.y;
            if (HEAD_SPLIT) {
                __half* Y = (__half*)Yv;
                __half2 h0 = __floats2half2_rn(r0.x * oscale, r0.y * oscale);
                __half2 h1 = __floats2half2_rn(r1.x * oscale, r1.y * oscale);
                const int h  = n >> 6;
                const int dd = n & 63;
                const int b1 = m >> 11;
                const int s1 = m & (SEQ - 1);
                *(__half2*)&Y[((size_t)(b1 * N_HEADS + h) * SEQ + s1) * DEPTH + dd] = h0;
                const int m2 = m + 8;
                const int b2 = m2 >> 11;
                const int s2 = m2 & (SEQ - 1);
                *(__half2*)&Y[((size_t)(b2 * N_HEADS + h) * SEQ + s2) * DEPTH + dd] = h1;
            } else {
                float* Y = (float*)Yv;
                *(float2*)&Y[(size_t)m * D_MODEL + n] = r0;
                *(float2*)&Y[(size_t)(m + 8) * D_MODEL + n] = r1;
            }
        }
    }
}

// ---------------------------------------------------------------------------
// Flash attention, fp16 mma m16n8k16 + ldmatrix feeds + register-resident P.
// 8 warps; warp w owns q-rows [16w,16w+16). BQ=128, BKV=64.
// q_s [128][72] halves; k_s/v_s 2-stage ping-pong [64][72] halves each.
// LDH=72 -> 9x16B row stride: every 8-row ldmatrix tile hits 8 distinct
// bank groups (9r mod 32 distinct for r=0..7). cp.async 16B chunks aligned.
// ---------------------------------------------------------------------------
#define LDH   72
#define KSTGH (64 * LDH)
#define FL_SMEM ((128 * LDH + 4 * KSTGH) * 2)   // 55296 B

__global__ __launch_bounds__(256, 2)
void flash_mma_kernel()
{
    extern __shared__ __half smh[];
    __half* q_s = smh;                  // [128][LDH]
    __half* k_s = q_s + 128 * LDH;      // 2 x [64][LDH]
    __half* v_s = k_s + 2 * KSTGH;      // 2 x [64][LDH]

    const int tid  = threadIdx.x;
    const int lane = tid & 31;
    const int w    = tid >> 5;
    const int g    = lane >> 2;
    const int t    = lane & 3;

    const int q0 = blockIdx.x * 128;
    const int bh = blockIdx.y;
    const int b  = bh >> 4;
    const int h  = bh & 15;

    const __half* gq = g_q + ((size_t)bh * SEQ + q0) * DEPTH;
    const __half* gk = g_k + (size_t)bh * SEQ * DEPTH;
    const __half* gv = g_v + (size_t)bh * SEQ * DEPTH;

    const uint32_t q_u = smem_u32(q_s);
    const uint32_t k_u = smem_u32(k_s);
    const uint32_t v_u = smem_u32(v_s);

    // K/V copy coords: 64 rows x 8 x 16B chunks = 512 / 256 threads = 2 each
    const int crow = tid >> 3;          // 0..31 (+32)
    const int cch  = tid & 7;           // 16B chunk in row

    // Prefetch chunk 0 into stage 0
    #pragma unroll
    for (int i = 0; i < 2; i++) {
        const int row = crow + i * 32;
        cp16(k_u + (uint32_t)(row * LDH + cch * 8) * 2u, gk + row * DEPTH + cch * 8);
        cp16(v_u + (uint32_t)(row * LDH + cch * 8) * 2u, gv + row * DEPTH + cch * 8);
    }
    CP_COMMIT();

    // Stage Q (SIMT copy, overlaps with cp.async): 128 rows x 8 chunks
    #pragma unroll
    for (int i = 0; i < 4; i++) {
        int id  = tid + i * 256;        // 0..1023
        int row = id >> 3;
        int ch  = id & 7;
        *(uint4*)&q_s[row * LDH + ch * 8] = *(const uint4*)&gq[row * DEPTH + ch * 8];
    }
    __syncthreads();

    // Preload Q A-frags (4 k-steps of 16)
    const int mr0 = w * 16 + g;
    const int mr1 = mr0 + 8;
    const uint32_t a_addr = q_u
        + (uint32_t)(((w * 16 + (lane & 15)) * LDH) + ((lane & 16) ? 8 : 0)) * 2u;
    uint32_t qf[4][4];
    #pragma unroll
    for (int ks = 0; ks < 4; ks++) ldsm4(qf[ks], a_addr + ks * 32u);

    // ldmatrix lane components for K (B-frag) and V (trans B-frag)
    const int krow_l = ((lane & 16) ? 8 : 0) + (lane & 7);
    const int kcol_l = (lane & 8) ? 8 : 0;
    const int vrow_l = ((lane & 8) ? 8 : 0) + (lane & 7);
    const int vcol_l = (lane & 16) ? 8 : 0;

    float of[8][4];
    #pragma unroll
    for (int nf = 0; nf < 8; nf++)
        #pragma unroll
        for (int r = 0; r < 4; r++) of[nf][r] = 0.0f;
    float m0r = -INFINITY, m1r = -INFINITY;
    float l0r = 0.0f, l1r = 0.0f;

    const int NCHK = SEQ / 64;   // 32
    for (int jc = 0; jc < NCHK; jc++) {
        const int p = jc & 1;

        if (jc + 1 < NCHK) {
            const __half* kp = gk + (size_t)(jc + 1) * 64 * DEPTH;
            const __half* vp = gv + (size_t)(jc + 1) * 64 * DEPTH;
            const uint32_t kd = k_u + (uint32_t)((p ^ 1) * KSTGH) * 2u;
            const uint32_t vd = v_u + (uint32_t)((p ^ 1) * KSTGH) * 2u;
            #pragma unroll
            for (int i = 0; i < 2; i++) {
                const int row = crow + i * 32;
                cp16(kd + (uint32_t)(row * LDH + cch * 8) * 2u, kp + row * DEPTH + cch * 8);
                cp16(vd + (uint32_t)(row * LDH + cch * 8) * 2u, vp + row * DEPTH + cch * 8);
            }
            CP_COMMIT();
            CP_WAIT(1);
        } else {
            CP_WAIT(0);
        }
        __syncthreads();

        const uint32_t kSu = k_u + (uint32_t)(p * KSTGH) * 2u;
        const uint32_t vSu = v_u + (uint32_t)(p * KSTGH) * 2u;

        // QK: S[16x64] per warp. 4 k-steps x 4 ldsm4 (2 n-frags each)
        float sf[8][4];
        #pragma unroll
        for (int nf = 0; nf < 8; nf++)
            #pragma unroll
            for (int r = 0; r < 4; r++) sf[nf][r] = 0.0f;

        #pragma unroll
        for (int ks = 0; ks < 4; ks++) {
            #pragma unroll
            for (int nfp = 0; nfp < 4; nfp++) {
                uint32_t bf[4];
                ldsm4(bf, kSu + (uint32_t)(((16 * nfp + krow_l) * LDH) + kcol_l + 16 * ks) * 2u);
                mma_f16(sf[2 * nfp],     qf[ks], &bf[0]);
                mma_f16(sf[2 * nfp + 1], qf[ks], &bf[2]);
            }
        }

        // Online softmax (rows mr0: c0,c1; mr1: c2,c3); shfl over t-lanes
        float mx0 = -INFINITY, mx1 = -INFINITY;
        #pragma unroll
        for (int nf = 0; nf < 8; nf++) {
            mx0 = fmaxf(mx0, fmaxf(sf[nf][0], sf[nf][1]));
            mx1 = fmaxf(mx1, fmaxf(sf[nf][2], sf[nf][3]));
        }
        mx0 = fmaxf(mx0, __shfl_xor_sync(0xffffffffu, mx0, 1));
        mx0 = fmaxf(mx0, __shfl_xor_sync(0xffffffffu, mx0, 2));
        mx1 = fmaxf(mx1, __shfl_xor_sync(0xffffffffu, mx1, 1));
        mx1 = fmaxf(mx1, __shfl_xor_sync(0xffffffffu, mx1, 2));

        const float mn0 = fmaxf(m0r, mx0);
        const float mn1 = fmaxf(m1r, mx1);
        const float al0 = __expf(m0r - mn0);
        const float al1 = __expf(m1r - mn1);
        m0r = mn0; m1r = mn1;

        // exp -> half2 (P stays in registers as A-frag halves), sums of the
        // ROUNDED values for numerator/denominator consistency
        uint32_t ph[8], pl[8];
        float rs0 = 0.0f, rs1 = 0.0f;
        #pragma unroll
        for (int nf = 0; nf < 8; nf++) {
            __half2 h0 = __floats2half2_rn(__expf(sf[nf][0] - mn0),
                                           __expf(sf[nf][1] - mn0));
            __half2 h1 = __floats2half2_rn(__expf(sf[nf][2] - mn1),
                                           __expf(sf[nf][3] - mn1));
            ph[nf] = *(uint32_t*)&h0;
            pl[nf] = *(uint32_t*)&h1;
            float2 f0 = __half22float2(h0);
            float2 f1 = __half22float2(h1);
            rs0 += f0.x + f0.y;
            rs1 += f1.x + f1.y;
        }
        rs0 += __shfl_xor_sync(0xffffffffu, rs0, 1);
        rs0 += __shfl_xor_sync(0xffffffffu, rs0, 2);
        rs1 += __shfl_xor_sync(0xffffffffu, rs1, 1);
        rs1 += __shfl_xor_sync(0xffffffffu, rs1, 2);
        l0r = l0r * al0 + rs0;
        l1r = l1r * al1 + rs1;

        #pragma unroll
        for (int nf = 0; nf < 8; nf++) {
            of[nf][0] *= al0; of[nf][1] *= al0;
            of[nf][2] *= al1; of[nf][3] *= al1;
        }

        // PV: O += P @ V. A from registers; B via ldmatrix.trans on V
        #pragma unroll
        for (int ks = 0; ks < 4; ks++) {
            uint32_t af[4] = {ph[2 * ks], pl[2 * ks], ph[2 * ks + 1], pl[2 * ks + 1]};
            #pragma unroll
            for (int nfp = 0; nfp < 4; nfp++) {
                uint32_t bf[4];
                ldsm4t(bf, vSu + (uint32_t)(((16 * ks + vrow_l) * LDH) + 16 * nfp + vcol_l) * 2u);
                mma_f16(of[2 * nfp],     af, &bf[0]);
                mma_f16(of[2 * nfp + 1], af, &bf[2]);
            }
        }
        __syncthreads();   // stage p fully consumed before refill next iter
    }

    // Epilogue: normalize, write fp32 [B,S,D] with heads re-interleaved
    const float inv0 = 1.0f / l0r;
    const float inv1 = 1.0f / l1r;
    const size_t r0base = (size_t)(b * SEQ + q0 + mr0) * D_MODEL + h * DEPTH;
    const size_t r1base = (size_t)(b * SEQ + q0 + mr1) * D_MODEL + h * DEPTH;
    #pragma unroll
    for (int nf = 0; nf < 8; nf++) {
        const int col = nf * 8 + 2 * t;
        *(float2*)&g_ao[r0base + col] = make_float2(of[nf][0] * inv0, of[nf][1] * inv0);
        *(float2*)&g_ao[r1base + col] = make_float2(of[nf][2] * inv1, of[nf][3] * inv1);
    }
}

// ---------------------------------------------------------------------------
// Launch
// ---------------------------------------------------------------------------
extern "C" void kernel_launch(void* const* d_in, const int* in_sizes, int n_in,
                              void* d_out, int out_size)
{
    const float* Q  = (const float*)d_in[0];
    const float* K  = (const float*)d_in[1];
    const float* V  = (const float*)d_in[2];
    const float* Wq = (const float*)d_in[3];
    const float* bq = (const float*)d_in[4];
    const float* Wk = (const float*)d_in[5];
    const float* bk = (const float*)d_in[6];
    const float* Wv = (const float*)d_in[7];
    const float* bv = (const float*)d_in[8];
    const float* Wo = (const float*)d_in[9];
    const float* bo = (const float*)d_in[10];
    float* out = (float*)d_out;

    void *gq, *gk, *gv, *gao;
    cudaGetSymbolAddress(&gq,  g_q);
    cudaGetSymbolAddress(&gk,  g_k);
    cudaGetSymbolAddress(&gv,  g_v);
    cudaGetSymbolAddress(&gao, g_ao);

    static bool attr_set = false;
    if (!attr_set) {
        cudaFuncSetAttribute(flash_mma_kernel,
                             cudaFuncAttributeMaxDynamicSharedMemorySize, FL_SMEM);
        attr_set = true;
    }

    const dim3 ggrid(D_MODEL / 128, M_TOT / 128);   // (8, 32)

    // Projections -> fp16 head-split scratch; Q pre-scaled by 1/8
    gemm_mma_kernel<1><<<ggrid, 256>>>(Q, Wq, bq, gq, 0.125f);
    gemm_mma_kernel<1><<<ggrid, 256>>>(K, Wk, bk, gk, 1.0f);
    gemm_mma_kernel<1><<<ggrid, 256>>>(V, Wv, bv, gv, 1.0f);

    // Flash attention (fp16 mma)
    flash_mma_kernel<<<dim3(SEQ / 128, BATCH * N_HEADS), 256, FL_SMEM>>>();

    // Output projection (tf32) -> d_out
    gemm_mma_kernel<0><<<ggrid, 256>>>((const float*)gao, Wo, bo, out, 1.0f);
}

// round 10
// speedup vs baseline: 1.9269x; 1.3123x over previous
#include <cuda_runtime.h>
#include <cuda_fp16.h>
#include <math.h>
#include <stdint.h>

#define D_MODEL 1024
#define N_HEADS 16
#define DEPTH   64
#define BATCH   2
#define SEQ     2048
#define M_TOT   (BATCH * SEQ)   // 4096

// ---------------------------------------------------------------------------
// Scratch (no cudaMalloc allowed): device globals
// g_q/g_k/g_v hold fp16 values (g_q pre-scaled by 0.125)
// ---------------------------------------------------------------------------
__device__ __half g_q[BATCH * N_HEADS * SEQ * DEPTH];   // [B,H,S,64]
__device__ __half g_k[BATCH * N_HEADS * SEQ * DEPTH];
__device__ __half g_v[BATCH * N_HEADS * SEQ * DEPTH];
__device__ float  g_ao[M_TOT * D_MODEL];                // attention out [B,S,D]

// ---------------------------------------------------------------------------
// PTX helpers (baseline features only — legal on sm_103 target)
// ---------------------------------------------------------------------------
__device__ __forceinline__ void mma_f16(float c[4], const uint32_t a[4],
                                        const uint32_t b[2]) {
    asm volatile(
        "mma.sync.aligned.m16n8k16.row.col.f32.f16.f16.f32 "
        "{%0,%1,%2,%3}, {%4,%5,%6,%7}, {%8,%9}, {%0,%1,%2,%3};\n"
        : "+f"(c[0]), "+f"(c[1]), "+f"(c[2]), "+f"(c[3])
        : "r"(a[0]), "r"(a[1]), "r"(a[2]), "r"(a[3]),
          "r"(b[0]), "r"(b[1]));
}

__device__ __forceinline__ void ldsm4(uint32_t r[4], uint32_t addr) {
    asm volatile("ldmatrix.sync.aligned.m8n8.x4.shared.b16 {%0,%1,%2,%3}, [%4];"
        : "=r"(r[0]), "=r"(r[1]), "=r"(r[2]), "=r"(r[3]) : "r"(addr));
}
__device__ __forceinline__ void ldsm4t(uint32_t r[4], uint32_t addr) {
    asm volatile("ldmatrix.sync.aligned.m8n8.x4.trans.shared.b16 {%0,%1,%2,%3}, [%4];"
        : "=r"(r[0]), "=r"(r[1]), "=r"(r[2]), "=r"(r[3]) : "r"(addr));
}

__device__ __forceinline__ uint32_t smem_u32(const void* p) {
    uint32_t a;
    asm("{ .reg .u64 t; cvta.to.shared.u64 t, %1; cvt.u32.u64 %0, t; }"
        : "=r"(a) : "l"(p));
    return a;
}

__device__ __forceinline__ void cp16(uint32_t dst, const void* src) {
    asm volatile("cp.async.ca.shared.global [%0], [%1], 16;"
                 :: "r"(dst), "l"(src) : "memory");
}
#define CP_COMMIT() asm volatile("cp.async.commit_group;" ::: "memory")
#define CP_WAIT(n)  asm volatile("cp.async.wait_group %0;" :: "n"(n) : "memory")

__device__ __forceinline__ uint32_t pack_h2(float x, float y) {
    __half2 h = __floats2half2_rn(x, y);
    return *(uint32_t*)&h;
}

// ---------------------------------------------------------------------------
// GEMM (fp16 mma m16n8k16, fp32 accumulate): Y = X @ W^T + bias
// X:[4096,1024] fp32, W:[1024,1024] fp32 — converted to fp16 at stage-in.
// Block 128x128, BK=32, double-buffered smem, 8 warps (2m x 4n), warp 64x32.
// smem halves, LD=40 -> 80B = 5x16B row stride (odd) -> conflict-free ldmatrix.
// HEAD_SPLIT=1: epilogue emits fp16 head-split layout (oscale folded).
// ---------------------------------------------------------------------------
#define GBK  32
#define GLDH 40
#define GSTG (128 * GLDH)   // halves per operand-stage (5120)

template <int HEAD_SPLIT>
__global__ __launch_bounds__(256, 2)
void gemm_f16_kernel(const float* __restrict__ X,
                     const float* __restrict__ W,
                     const float* __restrict__ bias,
                     void* __restrict__ Yv,
                     float oscale)
{
    __shared__ __half sA[2][GSTG];
    __shared__ __half sB[2][GSTG];

    const int tid  = threadIdx.x;
    const int lane = tid & 31;
    const int wid  = tid >> 5;
    const int wm   = wid & 1;     // 0..1 (m warp)
    const int wn   = wid >> 1;    // 0..3 (n warp)
    const int g    = lane >> 2;
    const int t    = lane & 3;
    const int m0   = blockIdx.y * 128;
    const int n0   = blockIdx.x * 128;

    // Loader coords: 128 rows x 8 float4-groups (32 floats) per operand;
    // 256 threads -> 4 (row,+32) groups each.
    const int lrow = tid >> 3;    // 0..31
    const int lc4  = tid & 7;     // float4 index within 32-float row chunk

    // ldmatrix lane coords (identical recipe to the proven flash kernel)
    const int arow = wm * 64 + (lane & 15);
    const int acol = (lane & 16) ? 8 : 0;
    const int brow = wn * 32 + ((lane & 16) ? 8 : 0) + (lane & 7);
    const int bcol = (lane & 8) ? 8 : 0;
    const uint32_t sA_u = smem_u32(sA);
    const uint32_t sB_u = smem_u32(sB);

    float cacc[4][4][4];
    #pragma unroll
    for (int mf = 0; mf < 4; mf++)
        #pragma unroll
        for (int nf = 0; nf < 4; nf++)
            #pragma unroll
            for (int r = 0; r < 4; r++) cacc[mf][nf][r] = 0.0f;

    const float* Xb = X + (size_t)m0 * D_MODEL;
    const float* Wb = W + (size_t)n0 * D_MODEL;

    uint2 ra[4], rb[4];   // 4 halves each (converted at load)

    // Prologue: load + convert chunk 0
    #pragma unroll
    for (int j = 0; j < 4; j++) {
        const int row = lrow + j * 32;
        float4 a = *(const float4*)(Xb + (size_t)row * D_MODEL + lc4 * 4);
        float4 b = *(const float4*)(Wb + (size_t)row * D_MODEL + lc4 * 4);
        ra[j] = make_uint2(pack_h2(a.x, a.y), pack_h2(a.z, a.w));
        rb[j] = make_uint2(pack_h2(b.x, b.y), pack_h2(b.z, b.w));
    }
    #pragma unroll
    for (int j = 0; j < 4; j++) {
        const int row = lrow + j * 32;
        *(uint2*)&sA[0][row * GLDH + lc4 * 4] = ra[j];
        *(uint2*)&sB[0][row * GLDH + lc4 * 4] = rb[j];
    }
    __syncthreads();

    const int NCH = D_MODEL / GBK;   // 32
    for (int c = 0; c < NCH; c++) {
        const int p = c & 1;
        if (c + 1 < NCH) {
            const int koff = (c + 1) * GBK;
            #pragma unroll
            for (int j = 0; j < 4; j++) {
                const int row = lrow + j * 32;
                float4 a = *(const float4*)(Xb + (size_t)row * D_MODEL + koff + lc4 * 4);
                float4 b = *(const float4*)(Wb + (size_t)row * D_MODEL + koff + lc4 * 4);
                ra[j] = make_uint2(pack_h2(a.x, a.y), pack_h2(a.z, a.w));
                rb[j] = make_uint2(pack_h2(b.x, b.y), pack_h2(b.z, b.w));
            }
        }

        const uint32_t aS = sA_u + (uint32_t)(p * GSTG) * 2u;
        const uint32_t bS = sB_u + (uint32_t)(p * GSTG) * 2u;
        #pragma unroll
        for (int ks = 0; ks < 2; ks++) {
            uint32_t af[4][4], bf[2][4];
            #pragma unroll
            for (int mf = 0; mf < 4; mf++)
                ldsm4(af[mf], aS + (uint32_t)(((arow + mf * 16) * GLDH) + acol + ks * 16) * 2u);
            #pragma unroll
            for (int nfp = 0; nfp < 2; nfp++)
                ldsm4(bf[nfp], bS + (uint32_t)(((brow + nfp * 16) * GLDH) + bcol + ks * 16) * 2u);
            #pragma unroll
            for (int mf = 0; mf < 4; mf++) {
                #pragma unroll
                for (int nfp = 0; nfp < 2; nfp++) {
                    mma_f16(cacc[mf][2 * nfp],     af[mf], &bf[nfp][0]);
                    mma_f16(cacc[mf][2 * nfp + 1], af[mf], &bf[nfp][2]);
                }
            }
        }

        if (c + 1 < NCH) {
            const int q = p ^ 1;
            #pragma unroll
            for (int j = 0; j < 4; j++) {
                const int row = lrow + j * 32;
                *(uint2*)&sA[q][row * GLDH + lc4 * 4] = ra[j];
                *(uint2*)&sB[q][row * GLDH + lc4 * 4] = rb[j];
            }
            __syncthreads();
        }
    }

    // Epilogue: add bias, store (C frag: c0=(g,2t) c1=(g,2t+1) c2/c3 rows +8)
    #pragma unroll
    for (int mf = 0; mf < 4; mf++) {
        #pragma unroll
        for (int nf = 0; nf < 4; nf++) {
            const int m = m0 + wm * 64 + mf * 16 + g;
            const int n = n0 + wn * 32 + nf * 8 + 2 * t;
            float2 bb = *(const float2*)&bias[n];
            float2 r0, r1;
            r0.x = cacc[mf][nf][0] + bb.x;
            r0.y = cacc[mf][nf][1] + bb.y;
            r1.x = cacc[mf][nf][2] + bb.x;
            r1.y = cacc[mf][nf][3] + bb.y;
            if (HEAD_SPLIT) {
                __half* Y = (__half*)Yv;
                __half2 h0 = __floats2half2_rn(r0.x * oscale, r0.y * oscale);
                __half2 h1 = __floats2half2_rn(r1.x * oscale, r1.y * oscale);
                const int h  = n >> 6;
                const int dd = n & 63;
                const int b1 = m >> 11;
                const int s1 = m & (SEQ - 1);
                *(__half2*)&Y[((size_t)(b1 * N_HEADS + h) * SEQ + s1) * DEPTH + dd] = h0;
                const int m2 = m + 8;
                const int b2 = m2 >> 11;
                const int s2 = m2 & (SEQ - 1);
                *(__half2*)&Y[((size_t)(b2 * N_HEADS + h) * SEQ + s2) * DEPTH + dd] = h1;
            } else {
                float* Y = (float*)Yv;
                *(float2*)&Y[(size_t)m * D_MODEL + n] = r0;
                *(float2*)&Y[(size_t)(m + 8) * D_MODEL + n] = r1;
            }
        }
    }
}

// ---------------------------------------------------------------------------
// Flash attention, fp16 mma m16n8k16 + ldmatrix feeds + register-resident P.
// (Unchanged from R9 — passing at 140us.)
// ---------------------------------------------------------------------------
#define LDH   72
#define KSTGH (64 * LDH)
#define FL_SMEM ((128 * LDH + 4 * KSTGH) * 2)   // 55296 B

__global__ __launch_bounds__(256, 2)
void flash_mma_kernel()
{
    extern __shared__ __half smh[];
    __half* q_s = smh;                  // [128][LDH]
    __half* k_s = q_s + 128 * LDH;      // 2 x [64][LDH]
    __half* v_s = k_s + 2 * KSTGH;      // 2 x [64][LDH]

    const int tid  = threadIdx.x;
    const int lane = tid & 31;
    const int w    = tid >> 5;
    const int g    = lane >> 2;
    const int t    = lane & 3;

    const int q0 = blockIdx.x * 128;
    const int bh = blockIdx.y;
    const int b  = bh >> 4;
    const int h  = bh & 15;

    const __half* gq = g_q + ((size_t)bh * SEQ + q0) * DEPTH;
    const __half* gk = g_k + (size_t)bh * SEQ * DEPTH;
    const __half* gv = g_v + (size_t)bh * SEQ * DEPTH;

    const uint32_t q_u = smem_u32(q_s);
    const uint32_t k_u = smem_u32(k_s);
    const uint32_t v_u = smem_u32(v_s);

    const int crow = tid >> 3;          // 0..31 (+32)
    const int cch  = tid & 7;

    #pragma unroll
    for (int i = 0; i < 2; i++) {
        const int row = crow + i * 32;
        cp16(k_u + (uint32_t)(row * LDH + cch * 8) * 2u, gk + row * DEPTH + cch * 8);
        cp16(v_u + (uint32_t)(row * LDH + cch * 8) * 2u, gv + row * DEPTH + cch * 8);
    }
    CP_COMMIT();

    #pragma unroll
    for (int i = 0; i < 4; i++) {
        int id  = tid + i * 256;
        int row = id >> 3;
        int ch  = id & 7;
        *(uint4*)&q_s[row * LDH + ch * 8] = *(const uint4*)&gq[row * DEPTH + ch * 8];
    }
    __syncthreads();

    const int mr0 = w * 16 + g;
    const int mr1 = mr0 + 8;
    const uint32_t a_addr = q_u
        + (uint32_t)(((w * 16 + (lane & 15)) * LDH) + ((lane & 16) ? 8 : 0)) * 2u;
    uint32_t qf[4][4];
    #pragma unroll
    for (int ks = 0; ks < 4; ks++) ldsm4(qf[ks], a_addr + ks * 32u);

    const int krow_l = ((lane & 16) ? 8 : 0) + (lane & 7);
    const int kcol_l = (lane & 8) ? 8 : 0;
    const int vrow_l = ((lane & 8) ? 8 : 0) + (lane & 7);
    const int vcol_l = (lane & 16) ? 8 : 0;

    float of[8][4];
    #pragma unroll
    for (int nf = 0; nf < 8; nf++)
        #pragma unroll
        for (int r = 0; r < 4; r++) of[nf][r] = 0.0f;
    float m0r = -INFINITY, m1r = -INFINITY;
    float l0r = 0.0f, l1r = 0.0f;

    const int NCHK = SEQ / 64;   // 32
    for (int jc = 0; jc < NCHK; jc++) {
        const int p = jc & 1;

        if (jc + 1 < NCHK) {
            const __half* kp = gk + (size_t)(jc + 1) * 64 * DEPTH;
            const __half* vp = gv + (size_t)(jc + 1) * 64 * DEPTH;
            const uint32_t kd = k_u + (uint32_t)((p ^ 1) * KSTGH) * 2u;
            const uint32_t vd = v_u + (uint32_t)((p ^ 1) * KSTGH) * 2u;
            #pragma unroll
            for (int i = 0; i < 2; i++) {
                const int row = crow + i * 32;
                cp16(kd + (uint32_t)(row * LDH + cch * 8) * 2u, kp + row * DEPTH + cch * 8);
                cp16(vd + (uint32_t)(row * LDH + cch * 8) * 2u, vp + row * DEPTH + cch * 8);
            }
            CP_COMMIT();
            CP_WAIT(1);
        } else {
            CP_WAIT(0);
        }
        __syncthreads();

        const uint32_t kSu = k_u + (uint32_t)(p * KSTGH) * 2u;
        const uint32_t vSu = v_u + (uint32_t)(p * KSTGH) * 2u;

        float sf[8][4];
        #pragma unroll
        for (int nf = 0; nf < 8; nf++)
            #pragma unroll
            for (int r = 0; r < 4; r++) sf[nf][r] = 0.0f;

        #pragma unroll
        for (int ks = 0; ks < 4; ks++) {
            #pragma unroll
            for (int nfp = 0; nfp < 4; nfp++) {
                uint32_t bf[4];
                ldsm4(bf, kSu + (uint32_t)(((16 * nfp + krow_l) * LDH) + kcol_l + 16 * ks) * 2u);
                mma_f16(sf[2 * nfp],     qf[ks], &bf[0]);
                mma_f16(sf[2 * nfp + 1], qf[ks], &bf[2]);
            }
        }

        float mx0 = -INFINITY, mx1 = -INFINITY;
        #pragma unroll
        for (int nf = 0; nf < 8; nf++) {
            mx0 = fmaxf(mx0, fmaxf(sf[nf][0], sf[nf][1]));
            mx1 = fmaxf(mx1, fmaxf(sf[nf][2], sf[nf][3]));
        }
        mx0 = fmaxf(mx0, __shfl_xor_sync(0xffffffffu, mx0, 1));
        mx0 = fmaxf(mx0, __shfl_xor_sync(0xffffffffu, mx0, 2));
        mx1 = fmaxf(mx1, __shfl_xor_sync(0xffffffffu, mx1, 1));
        mx1 = fmaxf(mx1, __shfl_xor_sync(0xffffffffu, mx1, 2));

        const float mn0 = fmaxf(m0r, mx0);
        const float mn1 = fmaxf(m1r, mx1);
        const float al0 = __expf(m0r - mn0);
        const float al1 = __expf(m1r - mn1);
        m0r = mn0; m1r = mn1;

        uint32_t ph[8], pl[8];
        float rs0 = 0.0f, rs1 = 0.0f;
        #pragma unroll
        for (int nf = 0; nf < 8; nf++) {
            __half2 h0 = __floats2half2_rn(__expf(sf[nf][0] - mn0),
                                           __expf(sf[nf][1] - mn0));
            __half2 h1 = __floats2half2_rn(__expf(sf[nf][2] - mn1),
                                           __expf(sf[nf][3] - mn1));
            ph[nf] = *(uint32_t*)&h0;
            pl[nf] = *(uint32_t*)&h1;
            float2 f0 = __half22float2(h0);
            float2 f1 = __half22float2(h1);
            rs0 += f0.x + f0.y;
            rs1 += f1.x + f1.y;
        }
        rs0 += __shfl_xor_sync(0xffffffffu, rs0, 1);
        rs0 += __shfl_xor_sync(0xffffffffu, rs0, 2);
        rs1 += __shfl_xor_sync(0xffffffffu, rs1, 1);
        rs1 += __shfl_xor_sync(0xffffffffu, rs1, 2);
        l0r = l0r * al0 + rs0;
        l1r = l1r * al1 + rs1;

        #pragma unroll
        for (int nf = 0; nf < 8; nf++) {
            of[nf][0] *= al0; of[nf][1] *= al0;
            of[nf][2] *= al1; of[nf][3] *= al1;
        }

        #pragma unroll
        for (int ks = 0; ks < 4; ks++) {
            uint32_t af[4] = {ph[2 * ks], pl[2 * ks], ph[2 * ks + 1], pl[2 * ks + 1]};
            #pragma unroll
            for (int nfp = 0; nfp < 4; nfp++) {
                uint32_t bf[4];
                ldsm4t(bf, vSu + (uint32_t)(((16 * ks + vrow_l) * LDH) + 16 * nfp + vcol_l) * 2u);
                mma_f16(of[2 * nfp],     af, &bf[0]);
                mma_f16(of[2 * nfp + 1], af, &bf[2]);
            }
        }
        __syncthreads();
    }

    const float inv0 = 1.0f / l0r;
    const float inv1 = 1.0f / l1r;
    const size_t r0base = (size_t)(b * SEQ + q0 + mr0) * D_MODEL + h * DEPTH;
    const size_t r1base = (size_t)(b * SEQ + q0 + mr1) * D_MODEL + h * DEPTH;
    #pragma unroll
    for (int nf = 0; nf < 8; nf++) {
        const int col = nf * 8 + 2 * t;
        *(float2*)&g_ao[r0base + col] = make_float2(of[nf][0] * inv0, of[nf][1] * inv0);
        *(float2*)&g_ao[r1base + col] = make_float2(of[nf][2] * inv1, of[nf][3] * inv1);
    }
}

// ---------------------------------------------------------------------------
// Launch
// ---------------------------------------------------------------------------
extern "C" void kernel_launch(void* const* d_in, const int* in_sizes, int n_in,
                              void* d_out, int out_size)
{
    const float* Q  = (const float*)d_in[0];
    const float* K  = (const float*)d_in[1];
    const float* V  = (const float*)d_in[2];
    const float* Wq = (const float*)d_in[3];
    const float* bq = (const float*)d_in[4];
    const float* Wk = (const float*)d_in[5];
    const float* bk = (const float*)d_in[6];
    const float* Wv = (const float*)d_in[7];
    const float* bv = (const float*)d_in[8];
    const float* Wo = (const float*)d_in[9];
    const float* bo = (const float*)d_in[10];
    float* out = (float*)d_out;

    void *gq, *gk, *gv, *gao;
    cudaGetSymbolAddress(&gq,  g_q);
    cudaGetSymbolAddress(&gk,  g_k);
    cudaGetSymbolAddress(&gv,  g_v);
    cudaGetSymbolAddress(&gao, g_ao);

    static bool attr_set = false;
    if (!attr_set) {
        cudaFuncSetAttribute(flash_mma_kernel,
                             cudaFuncAttributeMaxDynamicSharedMemorySize, FL_SMEM);
        attr_set = true;
    }

    const dim3 ggrid(D_MODEL / 128, M_TOT / 128);   // (8, 32)

    // Projections (fp16 mma) -> fp16 head-split scratch; Q pre-scaled by 1/8
    gemm_f16_kernel<1><<<ggrid, 256>>>(Q, Wq, bq, gq, 0.125f);
    gemm_f16_kernel<1><<<ggrid, 256>>>(K, Wk, bk, gk, 1.0f);
    gemm_f16_kernel<1><<<ggrid, 256>>>(V, Wv, bv, gv, 1.0f);

    // Flash attention (fp16 mma)
    flash_mma_kernel<<<dim3(SEQ / 128, BATCH * N_HEADS), 256, FL_SMEM>>>();

    // Output projection (fp16 mma) -> d_out
    gemm_f16_kernel<0><<<ggrid, 256>>>((const float*)gao, Wo, bo, out, 1.0f);
}